// round 15
// baseline (speedup 1.0000x reference)
#include <cuda_runtime.h>

// ---------------- scratch (static device globals; no allocation) ----------
#define MAXN 200704
// per-node 16B record: {128*cnt + s0, s1, s2, s3} — count folded into lane 0
// via exact-decodable bias (one RED.128 per edge).
__device__ __align__(16) float g_acc[MAXN * 4];
// gate buffer: g_q[h*MAXN + n] = {I,F,G,O} of (h0@Whh^T + b) for channel h.
// float4 per (h, node): coalesced ST.128 in gemv, coalesced LDG.128 in k_node.
__device__ __align__(16) float4 g_q[32ll * MAXN];

typedef unsigned long long u64;

#define CNT_BIAS 128.0f
#define CNT_INV  (1.0f / 128.0f)

// ---------------- fast math helpers --------------------------------------
__device__ __forceinline__ float fexp(float x) {
    float y;
    asm("ex2.approx.f32 %0, %1;" : "=f"(y) : "f"(x * 1.4426950408889634f));
    return y;
}
__device__ __forceinline__ float frcp(float x) {
    float y;
    asm("rcp.approx.f32 %0, %1;" : "=f"(y) : "f"(x));
    return y;
}
__device__ __forceinline__ float sigf(float x)   { return frcp(1.0f + fexp(-x)); }
__device__ __forceinline__ float tanhf_f(float x){ return 2.0f * sigf(2.0f * x) - 1.0f; }

// packed f32x2 helpers
__device__ __forceinline__ u64 pk2(float a, float b) {
    u64 r; asm("mov.b64 %0, {%1,%2};" : "=l"(r) : "f"(a), "f"(b)); return r;
}
__device__ __forceinline__ void upk2(u64 v, float& a, float& b) {
    asm("mov.b64 {%0,%1}, %2;" : "=f"(a), "=f"(b) : "l"(v));
}
__device__ __forceinline__ u64 fma2(u64 a, u64 b, u64 c) {
    u64 d; asm("fma.rn.f32x2 %0, %1, %2, %3;" : "=l"(d) : "l"(a), "l"(b), "l"(c));
    return d;
}

// ---------------- fused kernel: edge scatter + Whh GEMV -------------------
// Every SPACING-th block is a GEMV block (M=1: 128 nodes/block, low regs so
// the SHARED register allocation keeps edge blocks at 8 blocks/SM); all
// other blocks scatter 512 edges. Interleaving keeps gemv blocks co-resident
// with the L2-atomic-bound edge blocks, using their idle FMA/LDS pipes.
__device__ __forceinline__ void scat(int d, float4 g, float we) {
    float* dp = &g_acc[4ll * d];
    asm volatile("red.global.add.v4.f32 [%0], {%1,%2,%3,%4};"
                 :: "l"(dp), "f"(CNT_BIAS + g.x * we), "f"(g.y * we),
                    "f"(g.z * we), "f"(g.w * we) : "memory");
}

__global__ void __launch_bounds__(128, 8)
k_fused(const void* __restrict__ ei, const float* __restrict__ w,
        const float* __restrict__ x, const float* __restrict__ h0,
        const float* __restrict__ lwhh,
        const float* __restrict__ lbih, const float* __restrict__ lbhh,
        int E, int N, int gblocks, int spacing) {
    __shared__ u64   s_whh[2048];   // lstm_w_hh natural fp32 u64 k-pairs
    __shared__ float s_b[128];      // bias (ih+hh)

    int bx = blockIdx.x;
    int t = threadIdx.x;
    bool is_gemv = ((bx % spacing) == 0) && ((bx / spacing) < gblocks);

    if (is_gemv) {
        // ---------------- GEMV role: 128 nodes, M=1 per thread ----------
        int gid = bx / spacing;
        const u64* src = (const u64*)lwhh;
        #pragma unroll
        for (int i = t; i < 2048; i += 128) s_whh[i] = src[i];
        if (t < 128) s_b[t] = lbih[t] + lbhh[t];
        __syncthreads();

        int n = gid * 128 + t;
        if (n >= N) return;

        u64 hp[16];
        {
            const float4* a = reinterpret_cast<const float4*>(h0) + 8ll * n;
            #pragma unroll
            for (int k = 0; k < 8; k++) {
                float4 u = a[k];
                hp[2*k] = pk2(u.x, u.y); hp[2*k+1] = pk2(u.z, u.w);
            }
        }

        float4* gq = &g_q[n];
        #pragma unroll 1
        for (int h = 0; h < 32; h++) {
            u64 aI = pk2(s_b[h],      0.0f);
            u64 aF = pk2(s_b[32 + h], 0.0f);
            u64 aG = pk2(s_b[64 + h], 0.0f);
            u64 aO = pk2(s_b[96 + h], 0.0f);
            const u64* wI = &s_whh[(h)      * 16];
            const u64* wF = &s_whh[(32 + h) * 16];
            const u64* wG = &s_whh[(64 + h) * 16];
            const u64* wO = &s_whh[(96 + h) * 16];
            #pragma unroll
            for (int kp = 0; kp < 16; kp += 2) {
                ulonglong2 vI = *(const ulonglong2*)&wI[kp];
                ulonglong2 vF = *(const ulonglong2*)&wF[kp];
                ulonglong2 vG = *(const ulonglong2*)&wG[kp];
                ulonglong2 vO = *(const ulonglong2*)&wO[kp];
                aI = fma2(hp[kp], vI.x, aI); aI = fma2(hp[kp+1], vI.y, aI);
                aF = fma2(hp[kp], vF.x, aF); aF = fma2(hp[kp+1], vF.y, aF);
                aG = fma2(hp[kp], vG.x, aG); aG = fma2(hp[kp+1], vG.y, aG);
                aO = fma2(hp[kp], vO.x, aO); aO = fma2(hp[kp+1], vO.y, aO);
            }
            float lo, hi, rI, rF, rG, rO;
            upk2(aI, lo, hi); rI = lo + hi;
            upk2(aF, lo, hi); rF = lo + hi;
            upk2(aG, lo, hi); rG = lo + hi;
            upk2(aO, lo, hi); rO = lo + hi;
            gq[(long long)h * MAXN] = make_float4(rI, rF, rG, rO);
        }
        return;
    }

    // ---------------- EDGE role: 512 edges per block ----------------------
    int ngemv_before = (bx + spacing - 1) / spacing;
    if (ngemv_before > gblocks) ngemv_before = gblocks;
    long long eid = bx - ngemv_before;

    // per-warp dtype sniff (1 extra load/lane, overlapped)
    int lane = t & 31;
    {
        const long long* q = (const long long*)ei;
        long long step = E >> 5; if (step < 1) step = 1;
        long long v = q[(long long)lane * step];
        bool okv = (v >= 0 && v < (long long)N);
        unsigned m = __ballot_sync(0xffffffffu, okv);
        lane = (m == 0xffffffffu) ? -1 : lane;
    }
    int is64 = (lane < 0);

    long long base = (eid * 128 + t) * 4;
    if (base >= E) return;
    const float4* __restrict__ xv = (const float4*)x;

    if (base + 4 <= E && (E & 3) == 0) {
        int s0, s1, s2, s3, d0, d1, d2, d3;
        if (is64) {
            const longlong2* p = (const longlong2*)ei;
            long long hs = base >> 1;
            longlong2 a0 = p[hs], a1 = p[hs + 1];
            long long ho = ((long long)E + base) >> 1;
            longlong2 b0 = p[ho], b1 = p[ho + 1];
            s0 = (int)a0.x; s1 = (int)a0.y; s2 = (int)a1.x; s3 = (int)a1.y;
            d0 = (int)b0.x; d1 = (int)b0.y; d2 = (int)b1.x; d3 = (int)b1.y;
        } else {
            const int4* p = (const int4*)ei;
            int4 a = p[base >> 2];
            int4 b = p[((long long)E + base) >> 2];
            s0 = a.x; s1 = a.y; s2 = a.z; s3 = a.w;
            d0 = b.x; d1 = b.y; d2 = b.z; d3 = b.w;
        }
        float4 wq = ((const float4*)w)[base >> 2];
        float4 g0 = xv[s0], g1 = xv[s1], g2 = xv[s2], g3 = xv[s3];
        scat(d0, g0, wq.x);
        scat(d1, g1, wq.y);
        scat(d2, g2, wq.z);
        scat(d3, g3, wq.w);
    } else {
        for (int j = 0; j < 4 && base + j < E; j++) {
            long long e = base + j;
            int src, dst;
            if (is64) {
                const long long* p = (const long long*)ei;
                src = (int)p[e];
                dst = (int)p[(long long)E + e];
            } else {
                const int* p = (const int*)ei;
                src = p[e];
                dst = p[E + e];
            }
            scat(dst, xv[src], w[e]);
        }
    }
}

// ---------------- kernel 2: light node update ------------------------------
// GRU + precomputed gate quads (32 coalesced LDG.128/thread) + wih fma2.
__global__ void __launch_bounds__(256, 4)
k_node(const float* __restrict__ x, const float* __restrict__ c0,
       const float* __restrict__ convw,
       const float* __restrict__ gwih, const float* __restrict__ gwhh,
       const float* __restrict__ gbih, const float* __restrict__ gbhh,
       const float* __restrict__ lwih,
       const float* __restrict__ linw, const float* __restrict__ linb,
       float* __restrict__ out, int N) {
    __shared__ u64   s_wih[256];    // lstm_w_ih natural fp32 u64 pairs
    __shared__ float  s_conv[16];
    __shared__ float4 s_gih[12];
    __shared__ float4 s_ghh[12];
    __shared__ float  s_gbi[12], s_gbh[12];
    __shared__ float  s_lin[32];
    __shared__ float  s_linb;

    int t = threadIdx.x;
    s_wih[t] = ((const u64*)lwih)[t];
    if (t < 32) s_lin[t] = linw[t];
    if (t < 16) s_conv[t] = convw[t];
    if (t < 12) {
        s_gih[t] = reinterpret_cast<const float4*>(gwih)[t];
        s_ghh[t] = reinterpret_cast<const float4*>(gwhh)[t];
        s_gbi[t] = gbih[t];
        s_gbh[t] = gbhh[t];
    }
    if (t == 0) s_linb = linb[0];
    __syncthreads();

    int n = blockIdx.x * 256 + t;
    if (n >= N) return;

    // ---- decode biased record: cnt and mean aggregation + conv 4x4 ----
    float4 sv = reinterpret_cast<const float4*>(g_acc)[n];
    float cnt = rintf(sv.x * CNT_INV);
    float s0  = sv.x - cnt * CNT_BIAS;
    float inv = frcp(fmaxf(cnt, 1.0f));
    float mx[4] = { s0 * inv, sv.y * inv, sv.z * inv, sv.w * inv };
    float agg[4];
    #pragma unroll
    for (int j = 0; j < 4; j++)
        agg[j] = mx[0] * s_conv[j] + mx[1] * s_conv[4 + j]
               + mx[2] * s_conv[8 + j] + mx[3] * s_conv[12 + j];

    const float4 xv4 = *reinterpret_cast<const float4*>(x + 4ll * n);
    float xa[4] = { xv4.x, xv4.y, xv4.z, xv4.w };

    // ---- GRU cell ----
    float hc[4];
    #pragma unroll
    for (int c = 0; c < 4; c++) {
        float4 wr = s_gih[c], wz = s_gih[4 + c], wn = s_gih[8 + c];
        float4 ur = s_ghh[c], uz = s_ghh[4 + c], un = s_ghh[8 + c];
        float ir = agg[0]*wr.x + agg[1]*wr.y + agg[2]*wr.z + agg[3]*wr.w + s_gbi[c];
        float iz = agg[0]*wz.x + agg[1]*wz.y + agg[2]*wz.z + agg[3]*wz.w + s_gbi[4 + c];
        float in_= agg[0]*wn.x + agg[1]*wn.y + agg[2]*wn.z + agg[3]*wn.w + s_gbi[8 + c];
        float hr = xa[0]*ur.x + xa[1]*ur.y + xa[2]*ur.z + xa[3]*ur.w + s_gbh[c];
        float hz = xa[0]*uz.x + xa[1]*uz.y + xa[2]*uz.z + xa[3]*uz.w + s_gbh[4 + c];
        float hn = xa[0]*un.x + xa[1]*un.y + xa[2]*un.z + xa[3]*un.w + s_gbh[8 + c];
        float r  = sigf(ir + hr);
        float z  = sigf(iz + hz);
        float nn = tanhf_f(in_ + r * hn);
        hc[c] = (1.0f - z) * nn + z * xa[c];
    }
    u64 hcp01 = pk2(hc[0], hc[1]);
    u64 hcp23 = pk2(hc[2], hc[3]);

    const float4* cp4 = reinterpret_cast<const float4*>(c0 + 32ll * n);
    const float4* gq = &g_q[n];
    float4* hout = reinterpret_cast<float4*>(out + (long long)N + 32ll * n);
    float4* cout = reinterpret_cast<float4*>(out + (long long)N + 32ll * N + 32ll * n);

    float oacc = 0.0f;
    #pragma unroll 1
    for (int hq = 0; hq < 8; hq++) {
        float4 cq = cp4[hq];
        float cpv[4] = { cq.x, cq.y, cq.z, cq.w };
        float hb[4], cb[4];
        #pragma unroll
        for (int j = 0; j < 4; j++) {
            int h = hq * 4 + j;
            float4 g = gq[(long long)h * MAXN];   // {I,F,G,O} coalesced
            u64 aI = fma2(hcp01, s_wih[h * 2],            pk2(g.x, 0.0f));
            aI     = fma2(hcp23, s_wih[h * 2 + 1],        aI);
            u64 aF = fma2(hcp01, s_wih[(32 + h) * 2],     pk2(g.y, 0.0f));
            aF     = fma2(hcp23, s_wih[(32 + h) * 2 + 1], aF);
            u64 aG = fma2(hcp01, s_wih[(64 + h) * 2],     pk2(g.z, 0.0f));
            aG     = fma2(hcp23, s_wih[(64 + h) * 2 + 1], aG);
            u64 aO = fma2(hcp01, s_wih[(96 + h) * 2],     pk2(g.w, 0.0f));
            aO     = fma2(hcp23, s_wih[(96 + h) * 2 + 1], aO);
            float lo, hi, ai, af, ag, ao;
            upk2(aI, lo, hi); ai = lo + hi;
            upk2(aF, lo, hi); af = lo + hi;
            upk2(aG, lo, hi); ag = lo + hi;
            upk2(aO, lo, hi); ao = lo + hi;
            float ig = sigf(ai), fg = sigf(af), og = sigf(ao), gg = tanhf_f(ag);
            float cn = fg * cpv[j] + ig * gg;
            float hn = og * tanhf_f(cn);
            cb[j] = cn; hb[j] = hn;
            oacc += fmaxf(hn, 0.0f) * s_lin[h];
        }
        cout[hq] = make_float4(cb[0], cb[1], cb[2], cb[3]);
        hout[hq] = make_float4(hb[0], hb[1], hb[2], hb[3]);
    }
    out[n] = oacc + s_linb;
}

// ---------------- launch -----------------------------------------------------
extern "C" void kernel_launch(void* const* d_in, const int* in_sizes, int n_in,
                              void* d_out, int out_size) {
    const float* x    = (const float*)d_in[0];
    const void*  ei   = d_in[1];
    const float* ew   = (const float*)d_in[2];
    const float* h0   = (const float*)d_in[3];
    const float* c0   = (const float*)d_in[4];
    const float* cw   = (const float*)d_in[5];
    const float* gwih = (const float*)d_in[6];
    const float* gwhh = (const float*)d_in[7];
    const float* gbih = (const float*)d_in[8];
    const float* gbhh = (const float*)d_in[9];
    const float* lwih = (const float*)d_in[10];
    const float* lwhh = (const float*)d_in[11];
    const float* lbih = (const float*)d_in[12];
    const float* lbhh = (const float*)d_in[13];
    const float* linw = (const float*)d_in[14];
    const float* linb = (const float*)d_in[15];

    int N = in_sizes[0] / 4;
    int E = in_sizes[2];
    if (N > MAXN) N = MAXN;

    float* out = (float*)d_out;

    // zero g_acc via one capturable async memset
    void* acc_ptr = nullptr;
    cudaGetSymbolAddress(&acc_ptr, g_acc);
    cudaMemsetAsync(acc_ptr, 0, (size_t)N * 4 * sizeof(float));

    int gblocks = (N + 127) / 128;                      // gemv blocks (128 nodes each)
    long long eth = ((long long)E + 3) / 4;             // edge threads
    int eblocks = (int)((eth + 127) / 128);             // 512 edges per block
    int total = eblocks + gblocks;
    int spacing = total / gblocks;                       // interleave period
    if (spacing < 1) spacing = 1;

    k_fused<<<total, 128>>>(ei, ew, x, h0, lwhh, lbih, lbhh,
                            E, N, gblocks, spacing);
    k_node<<<(N + 255) / 256, 256>>>(x, c0, cw, gwih, gwhh, gbih, gbhh,
                                     lwih, linw, linb, out, N);
}

// round 17
// speedup vs baseline: 1.2013x; 1.2013x over previous
#include <cuda_runtime.h>

// ---------------- scratch (static device globals; no allocation) ----------
#define MAXN 200704
// per-node 16B record: {128*cnt + s0, s1, s2, s3} — count folded into lane 0
// via exact-decodable bias (one RED.128 per edge).
__device__ __align__(16) float g_acc[MAXN * 4];

typedef unsigned long long u64;

#define CNT_BIAS 128.0f
#define CNT_INV  (1.0f / 128.0f)

// ---------------- fast math helpers --------------------------------------
__device__ __forceinline__ float fexp(float x) {
    float y;
    asm("ex2.approx.f32 %0, %1;" : "=f"(y) : "f"(x * 1.4426950408889634f));
    return y;
}
__device__ __forceinline__ float frcp(float x) {
    float y;
    asm("rcp.approx.f32 %0, %1;" : "=f"(y) : "f"(x));
    return y;
}
__device__ __forceinline__ float sigf(float x)   { return frcp(1.0f + fexp(-x)); }
__device__ __forceinline__ float tanhf_f(float x){ return 2.0f * sigf(2.0f * x) - 1.0f; }

// packed f32x2 helpers
__device__ __forceinline__ u64 pk2(float a, float b) {
    u64 r; asm("mov.b64 %0, {%1,%2};" : "=l"(r) : "f"(a), "f"(b)); return r;
}
__device__ __forceinline__ void upk2(u64 v, float& a, float& b) {
    asm("mov.b64 {%0,%1}, %2;" : "=f"(a), "=f"(b) : "l"(v));
}
__device__ __forceinline__ u64 fma2(u64 a, u64 b, u64 c) {
    u64 d; asm("fma.rn.f32x2 %0, %1, %2, %3;" : "=l"(d) : "l"(a), "l"(b), "l"(c));
    return d;
}

// ---------------- kernel 1: edge scatter (8 edges / thread) ---------------
// ONE RED.128 per edge: lane0 carries CNT_BIAS + w*x0 (count via bias).
// 8 edges/thread halves thread count and fixed per-thread overhead, doubles
// per-thread MLP (8 outstanding gathers before the RED burst).
__device__ __forceinline__ void scat(int d, float4 g, float we) {
    float* dp = &g_acc[4ll * d];
    asm volatile("red.global.add.v4.f32 [%0], {%1,%2,%3,%4};"
                 :: "l"(dp), "f"(CNT_BIAS + g.x * we), "f"(g.y * we),
                    "f"(g.z * we), "f"(g.w * we) : "memory");
}

__global__ void __launch_bounds__(256)
k_edge(const void* __restrict__ ei, const float* __restrict__ w,
       const float* __restrict__ x, int E, int N) {
    // ---- per-warp dtype sniff (1 extra load/lane, overlapped) ----
    int lane = threadIdx.x & 31;
    {
        const long long* q = (const long long*)ei;
        long long step = E >> 5; if (step < 1) step = 1;
        long long v = q[(long long)lane * step];
        bool okv = (v >= 0 && v < (long long)N);
        unsigned m = __ballot_sync(0xffffffffu, okv);
        lane = (m == 0xffffffffu) ? -1 : lane;
    }
    int is64 = (lane < 0);

    long long base = (long long)(blockIdx.x * 256 + threadIdx.x) * 8;
    if (base >= E) return;
    const float4* __restrict__ xv = (const float4*)x;

    if (base + 8 <= E && (E & 7) == 0) {
        int s[8], d[8];
        if (is64) {
            const longlong2* p = (const longlong2*)ei;
            long long hs = base >> 1;
            long long ho = ((long long)E + base) >> 1;
            #pragma unroll
            for (int q = 0; q < 4; q++) {
                longlong2 a = p[hs + q];
                longlong2 b = p[ho + q];
                s[2*q] = (int)a.x; s[2*q + 1] = (int)a.y;
                d[2*q] = (int)b.x; d[2*q + 1] = (int)b.y;
            }
        } else {
            const int4* p = (const int4*)ei;
            long long hs = base >> 2;
            long long ho = ((long long)E + base) >> 2;
            #pragma unroll
            for (int q = 0; q < 2; q++) {
                int4 a = p[hs + q];
                int4 b = p[ho + q];
                s[4*q] = a.x; s[4*q+1] = a.y; s[4*q+2] = a.z; s[4*q+3] = a.w;
                d[4*q] = b.x; d[4*q+1] = b.y; d[4*q+2] = b.z; d[4*q+3] = b.w;
            }
        }
        float4 w0 = ((const float4*)w)[base >> 2];
        float4 w1 = ((const float4*)w)[(base >> 2) + 1];
        float wv[8] = { w0.x, w0.y, w0.z, w0.w, w1.x, w1.y, w1.z, w1.w };

        // issue all 8 gathers first for MLP, then the RED burst
        float4 g[8];
        #pragma unroll
        for (int q = 0; q < 8; q++) g[q] = xv[s[q]];
        #pragma unroll
        for (int q = 0; q < 8; q++) scat(d[q], g[q], wv[q]);
    } else {
        for (int j = 0; j < 8 && base + j < E; j++) {
            long long e = base + j;
            int src, dst;
            if (is64) {
                const long long* p = (const long long*)ei;
                src = (int)p[e];
                dst = (int)p[(long long)E + e];
            } else {
                const int* p = (const int*)ei;
                src = p[e];
                dst = p[E + e];
            }
            scat(dst, xv[src], w[e]);
        }
    }
}

// ---------------- kernel 2: fused node update, 2 nodes / thread -----------
// (byte-identical to the proven 83us R10 kernel)
__global__ void __launch_bounds__(128, 4)
k_node(const float* __restrict__ x,
       const float* __restrict__ h0, const float* __restrict__ c0,
       const float* __restrict__ convw,
       const float* __restrict__ gwih, const float* __restrict__ gwhh,
       const float* __restrict__ gbih, const float* __restrict__ gbhh,
       const float* __restrict__ lwih, const float* __restrict__ lwhh,
       const float* __restrict__ lbih, const float* __restrict__ lbhh,
       const float* __restrict__ linw, const float* __restrict__ linb,
       float* __restrict__ out, int N) {
    __shared__ u64   s_whh[2048];   // lstm_w_hh natural: [row*16 + kp], row=g*32+h
    __shared__ u64   s_wih[256];    // lstm_w_ih natural: [row*2 + p]
    __shared__ float s_b[128];      // lstm bias (ih+hh)
    __shared__ float  s_conv[16];
    __shared__ float4 s_gih[12];
    __shared__ float4 s_ghh[12];
    __shared__ float  s_gbi[12], s_gbh[12];
    __shared__ float  s_lin[32];
    __shared__ float  s_linb;

    int t = threadIdx.x;
    {
        const u64* src = (const u64*)lwhh;
        #pragma unroll
        for (int i = t; i < 2048; i += 128) s_whh[i] = src[i];
        s_wih[t]       = ((const u64*)lwih)[t];
        s_wih[t + 128] = ((const u64*)lwih)[t + 128];
    }
    if (t < 128) s_b[t] = lbih[t] + lbhh[t];
    if (t < 32) s_lin[t] = linw[t];
    if (t < 16) s_conv[t] = convw[t];
    if (t < 12) {
        s_gih[t] = reinterpret_cast<const float4*>(gwih)[t];
        s_ghh[t] = reinterpret_cast<const float4*>(gwhh)[t];
        s_gbi[t] = gbih[t];
        s_gbh[t] = gbhh[t];
    }
    if (t == 0) s_linb = linb[0];
    __syncthreads();

    int n0 = blockIdx.x * 256 + t;
    int n1 = n0 + 128;
    bool v0 = (n0 < N), v1 = (n1 < N);
    if (!v0) return;
    int nc0 = n0;
    int nc1 = v1 ? n1 : n0;

    // ---- GRU for both nodes ----
    u64 hcp01[2], hcp23[2];
    #pragma unroll
    for (int m = 0; m < 2; m++) {
        int nn = m ? nc1 : nc0;
        float4 sv = reinterpret_cast<const float4*>(g_acc)[nn];
        float cnt = rintf(sv.x * CNT_INV);
        float sa  = sv.x - cnt * CNT_BIAS;
        float inv = frcp(fmaxf(cnt, 1.0f));
        float mx[4] = { sa * inv, sv.y * inv, sv.z * inv, sv.w * inv };
        float agg[4];
        #pragma unroll
        for (int j = 0; j < 4; j++)
            agg[j] = mx[0] * s_conv[j] + mx[1] * s_conv[4 + j]
                   + mx[2] * s_conv[8 + j] + mx[3] * s_conv[12 + j];

        const float4 xv4 = *reinterpret_cast<const float4*>(x + 4ll * nn);
        float xa[4] = { xv4.x, xv4.y, xv4.z, xv4.w };

        float hc[4];
        #pragma unroll
        for (int c = 0; c < 4; c++) {
            float4 wr = s_gih[c], wz = s_gih[4 + c], wn = s_gih[8 + c];
            float4 ur = s_ghh[c], uz = s_ghh[4 + c], un = s_ghh[8 + c];
            float ir = agg[0]*wr.x + agg[1]*wr.y + agg[2]*wr.z + agg[3]*wr.w + s_gbi[c];
            float iz = agg[0]*wz.x + agg[1]*wz.y + agg[2]*wz.z + agg[3]*wz.w + s_gbi[4 + c];
            float in_= agg[0]*wn.x + agg[1]*wn.y + agg[2]*wn.z + agg[3]*wn.w + s_gbi[8 + c];
            float hr = xa[0]*ur.x + xa[1]*ur.y + xa[2]*ur.z + xa[3]*ur.w + s_gbh[c];
            float hz = xa[0]*uz.x + xa[1]*uz.y + xa[2]*uz.z + xa[3]*uz.w + s_gbh[4 + c];
            float hn = xa[0]*un.x + xa[1]*un.y + xa[2]*un.z + xa[3]*un.w + s_gbh[8 + c];
            float r  = sigf(ir + hr);
            float z  = sigf(iz + hz);
            float nn2 = tanhf_f(in_ + r * hn);
            hc[c] = (1.0f - z) * nn2 + z * xa[c];
        }
        hcp01[m] = pk2(hc[0], hc[1]);
        hcp23[m] = pk2(hc[2], hc[3]);
    }

    // ---- h_prev for both nodes as natural k-pairs (64 regs) ----
    u64 hp0[16], hp1[16];
    {
        const float4* a = reinterpret_cast<const float4*>(h0) + 8ll * nc0;
        const float4* b = reinterpret_cast<const float4*>(h0) + 8ll * nc1;
        #pragma unroll
        for (int k = 0; k < 8; k++) {
            float4 u = a[k];
            hp0[2*k] = pk2(u.x, u.y); hp0[2*k+1] = pk2(u.z, u.w);
            float4 v = b[k];
            hp1[2*k] = pk2(v.x, v.y); hp1[2*k+1] = pk2(v.z, v.w);
        }
    }

    const float4* cpa = reinterpret_cast<const float4*>(c0 + 32ll * nc0);
    const float4* cpb = reinterpret_cast<const float4*>(c0 + 32ll * nc1);
    float4* hout0 = reinterpret_cast<float4*>(out + (long long)N + 32ll * n0);
    float4* cout0 = reinterpret_cast<float4*>(out + (long long)N + 32ll * N + 32ll * n0);
    float4* hout1 = reinterpret_cast<float4*>(out + (long long)N + 32ll * nc1);
    float4* cout1 = reinterpret_cast<float4*>(out + (long long)N + 32ll * N + 32ll * nc1);

    float oacc0 = 0.0f, oacc1 = 0.0f;
    #pragma unroll 1
    for (int hq = 0; hq < 8; hq++) {
        float4 cq0 = cpa[hq], cq1 = cpb[hq];
        float cpv0[4] = { cq0.x, cq0.y, cq0.z, cq0.w };
        float cpv1[4] = { cq1.x, cq1.y, cq1.z, cq1.w };
        float hb0[4], cb0[4], hb1[4], cb1[4];
        #pragma unroll
        for (int j = 0; j < 4; j++) {
            int h = hq * 4 + j;
            u64 bI = pk2(s_b[h],      0.0f);
            u64 bF = pk2(s_b[32 + h], 0.0f);
            u64 bG = pk2(s_b[64 + h], 0.0f);
            u64 bO = pk2(s_b[96 + h], 0.0f);
            u64 wi0 = s_wih[h * 2],            wi1 = s_wih[h * 2 + 1];
            u64 wf0 = s_wih[(32 + h) * 2],     wf1 = s_wih[(32 + h) * 2 + 1];
            u64 wg0 = s_wih[(64 + h) * 2],     wg1 = s_wih[(64 + h) * 2 + 1];
            u64 wo0 = s_wih[(96 + h) * 2],     wo1 = s_wih[(96 + h) * 2 + 1];

            u64 aI0 = fma2(hcp01[0], wi0, bI); aI0 = fma2(hcp23[0], wi1, aI0);
            u64 aF0 = fma2(hcp01[0], wf0, bF); aF0 = fma2(hcp23[0], wf1, aF0);
            u64 aG0 = fma2(hcp01[0], wg0, bG); aG0 = fma2(hcp23[0], wg1, aG0);
            u64 aO0 = fma2(hcp01[0], wo0, bO); aO0 = fma2(hcp23[0], wo1, aO0);
            u64 aI1 = fma2(hcp01[1], wi0, bI); aI1 = fma2(hcp23[1], wi1, aI1);
            u64 aF1 = fma2(hcp01[1], wf0, bF); aF1 = fma2(hcp23[1], wf1, aF1);
            u64 aG1 = fma2(hcp01[1], wg0, bG); aG1 = fma2(hcp23[1], wg1, aG1);
            u64 aO1 = fma2(hcp01[1], wo0, bO); aO1 = fma2(hcp23[1], wo1, aO1);

            const u64* wI = &s_whh[(h)      * 16];
            const u64* wF = &s_whh[(32 + h) * 16];
            const u64* wG = &s_whh[(64 + h) * 16];
            const u64* wO = &s_whh[(96 + h) * 16];
            #pragma unroll
            for (int kp = 0; kp < 16; kp += 2) {
                ulonglong2 vI = *(const ulonglong2*)&wI[kp];
                ulonglong2 vF = *(const ulonglong2*)&wF[kp];
                ulonglong2 vG = *(const ulonglong2*)&wG[kp];
                ulonglong2 vO = *(const ulonglong2*)&wO[kp];
                aI0 = fma2(hp0[kp], vI.x, aI0); aI0 = fma2(hp0[kp+1], vI.y, aI0);
                aI1 = fma2(hp1[kp], vI.x, aI1); aI1 = fma2(hp1[kp+1], vI.y, aI1);
                aF0 = fma2(hp0[kp], vF.x, aF0); aF0 = fma2(hp0[kp+1], vF.y, aF0);
                aF1 = fma2(hp1[kp], vF.x, aF1); aF1 = fma2(hp1[kp+1], vF.y, aF1);
                aG0 = fma2(hp0[kp], vG.x, aG0); aG0 = fma2(hp0[kp+1], vG.y, aG0);
                aG1 = fma2(hp1[kp], vG.x, aG1); aG1 = fma2(hp1[kp+1], vG.y, aG1);
                aO0 = fma2(hp0[kp], vO.x, aO0); aO0 = fma2(hp0[kp+1], vO.y, aO0);
                aO1 = fma2(hp1[kp], vO.x, aO1); aO1 = fma2(hp1[kp+1], vO.y, aO1);
            }

            float lo, hi, ai, af, ag, ao;
            upk2(aI0, lo, hi); ai = lo + hi;
            upk2(aF0, lo, hi); af = lo + hi;
            upk2(aG0, lo, hi); ag = lo + hi;
            upk2(aO0, lo, hi); ao = lo + hi;
            {
                float ig = sigf(ai), fg = sigf(af), og = sigf(ao), gg = tanhf_f(ag);
                float cn = fg * cpv0[j] + ig * gg;
                float hn = og * tanhf_f(cn);
                cb0[j] = cn; hb0[j] = hn;
                oacc0 += fmaxf(hn, 0.0f) * s_lin[h];
            }
            upk2(aI1, lo, hi); ai = lo + hi;
            upk2(aF1, lo, hi); af = lo + hi;
            upk2(aG1, lo, hi); ag = lo + hi;
            upk2(aO1, lo, hi); ao = lo + hi;
            {
                float ig = sigf(ai), fg = sigf(af), og = sigf(ao), gg = tanhf_f(ag);
                float cn = fg * cpv1[j] + ig * gg;
                float hn = og * tanhf_f(cn);
                cb1[j] = cn; hb1[j] = hn;
                oacc1 += fmaxf(hn, 0.0f) * s_lin[h];
            }
        }
        cout0[hq] = make_float4(cb0[0], cb0[1], cb0[2], cb0[3]);
        hout0[hq] = make_float4(hb0[0], hb0[1], hb0[2], hb0[3]);
        if (v1) {
            cout1[hq] = make_float4(cb1[0], cb1[1], cb1[2], cb1[3]);
            hout1[hq] = make_float4(hb1[0], hb1[1], hb1[2], hb1[3]);
        }
    }
    out[n0] = oacc0 + s_linb;
    if (v1) out[n1] = oacc1 + s_linb;
}

// ---------------- launch -----------------------------------------------------
extern "C" void kernel_launch(void* const* d_in, const int* in_sizes, int n_in,
                              void* d_out, int out_size) {
    const float* x    = (const float*)d_in[0];
    const void*  ei   = d_in[1];
    const float* ew   = (const float*)d_in[2];
    const float* h0   = (const float*)d_in[3];
    const float* c0   = (const float*)d_in[4];
    const float* cw   = (const float*)d_in[5];
    const float* gwih = (const float*)d_in[6];
    const float* gwhh = (const float*)d_in[7];
    const float* gbih = (const float*)d_in[8];
    const float* gbhh = (const float*)d_in[9];
    const float* lwih = (const float*)d_in[10];
    const float* lwhh = (const float*)d_in[11];
    const float* lbih = (const float*)d_in[12];
    const float* lbhh = (const float*)d_in[13];
    const float* linw = (const float*)d_in[14];
    const float* linb = (const float*)d_in[15];

    int N = in_sizes[0] / 4;
    int E = in_sizes[2];
    if (N > MAXN) N = MAXN;

    float* out = (float*)d_out;

    // zero the scratch buffer via one capturable async memset
    void* acc_ptr = nullptr;
    cudaGetSymbolAddress(&acc_ptr, g_acc);
    cudaMemsetAsync(acc_ptr, 0, (size_t)N * 4 * sizeof(float));

    long long nth = ((long long)E + 7) / 8;
    int eblocks = (int)((nth + 255) / 256);
    k_edge<<<eblocks, 256>>>(ei, ew, x, E, N);
    k_node<<<(N + 255) / 256, 128>>>(x, h0, c0, cw, gwih, gwhh, gbih, gbhh,
                                     lwih, lwhh, lbih, lbhh, linw, linb,
                                     out, N);
}